// round 2
// baseline (speedup 1.0000x reference)
#include <cuda_runtime.h>

// Problem constants (fixed dataset: B=16384, S=8, D=128, P=65536)
#define SB 8            // samples per item
#define DD 128          // embedding dim
#define ROW_F4 (DD / 4) // 32 float4 per row
#define PAIRS_PER_BLOCK 8
#define MAX_ROWS (16384 * SB)
#define MAX_BLOCKS 8192
#define EPSV 1e-6f

__device__ float g_norms[MAX_ROWS];
__device__ float g_block_sums[MAX_BLOCKS];

// ---------------------------------------------------------------------------
// Kernel 1: per-row squared norms. One warp per row (128 floats = 32 x float4).
// ---------------------------------------------------------------------------
__global__ void __launch_bounds__(256) norm_kernel(const float* __restrict__ z, int rows) {
    int warp = (blockIdx.x * 256 + threadIdx.x) >> 5;
    int lane = threadIdx.x & 31;
    if (warp >= rows) return;
    float4 v = reinterpret_cast<const float4*>(z)[warp * ROW_F4 + lane];
    float s = fmaf(v.x, v.x, fmaf(v.y, v.y, fmaf(v.z, v.z, v.w * v.w)));
#pragma unroll
    for (int m = 16; m; m >>= 1) s += __shfl_xor_sync(0xffffffffu, s, m);
    if (lane == 0) g_norms[warp] = s;
}

// ---------------------------------------------------------------------------
// Multi-value butterfly reduction stage: halves the live value count, pairing
// lane with lane^M. After stages 16,8,4,2,1 on 32 values, lane l holds the
// fully-reduced value with original index v == l in acc[0].
// ---------------------------------------------------------------------------
template <int M>
__device__ __forceinline__ void bfly(float* acc, int lane) {
    bool hi = (lane & M) != 0;
#pragma unroll
    for (int t = 0; t < M; t++) {
        float send = hi ? acc[t] : acc[t + M];
        float recv = __shfl_xor_sync(0xffffffffu, send, M);
        acc[t] = (hi ? acc[t + M] : acc[t]) + recv;
    }
}

// ---------------------------------------------------------------------------
// Kernel 2: main HIB criterion. One warp per pair index.
//   lane owns k-chunk [4*lane, 4*lane+4) of D=128.
//   Per matrix: load 16 rows (16 x LDG.128), 2 half-Gram (8x4) accumulations,
//   butterfly-reduce, pointwise sigmoid/log, accumulate.
// ---------------------------------------------------------------------------
__global__ void __launch_bounds__(256) hib_kernel(
    const float* __restrict__ z,
    const float* __restrict__ alpha_p,
    const float* __restrict__ beta_p,
    const int* __restrict__ ap, const int* __restrict__ pp,
    const int* __restrict__ an, const int* __restrict__ nn,
    int P)
{
    int lane = threadIdx.x & 31;
    int wib  = threadIdx.x >> 5;
    int pair = blockIdx.x * PAIRS_PER_BLOCK + wib;

    float beta = __ldg(beta_p);
    float a = log1pf(__expf(__ldg(alpha_p)));  // softplus(alpha)

    float total = 0.0f;

    if (pair < P) {
        int iA[2], iB[2];
        iA[0] = __ldg(ap + pair); iB[0] = __ldg(pp + pair);
        iA[1] = __ldg(an + pair); iB[1] = __ldg(nn + pair);

#pragma unroll
        for (int m = 0; m < 2; m++) {
            const float4* Za = reinterpret_cast<const float4*>(z) + (size_t)iA[m] * (SB * ROW_F4);
            const float4* Zb = reinterpret_cast<const float4*>(z) + (size_t)iB[m] * (SB * ROW_F4);
            float4 av[SB], bv[SB];
#pragma unroll
            for (int i = 0; i < SB; i++) av[i] = Za[i * ROW_F4 + lane];
#pragma unroll
            for (int j = 0; j < SB; j++) bv[j] = Zb[j * ROW_F4 + lane];

            // row index this lane will own after the butterfly: i = lane>>2
            float na = g_norms[iA[m] * SB + (lane >> 2)];

#pragma unroll
            for (int h = 0; h < 2; h++) {           // j in [4h, 4h+4)
                float acc[32];
#pragma unroll
                for (int i = 0; i < SB; i++) {
#pragma unroll
                    for (int jj = 0; jj < 4; jj++) {
                        float4 x = av[i];
                        float4 y = bv[h * 4 + jj];
                        acc[i * 4 + jj] =
                            fmaf(x.x, y.x, fmaf(x.y, y.y, fmaf(x.z, y.z, x.w * y.w)));
                    }
                }
                bfly<16>(acc, lane);
                bfly<8>(acc, lane);
                bfly<4>(acc, lane);
                bfly<2>(acc, lane);
                bfly<1>(acc, lane);
                // lane now holds dot(i=lane>>2, j=4h+(lane&3)) in acc[0]
                float nb = g_norms[iB[m] * SB + h * 4 + (lane & 3)];
                float d2 = na + nb - 2.0f * acc[0];
                float y0 = fmaf(-a, d2, beta);       // -a*d2 + beta
                float term;
                if (m == 0) {
                    // -log(sigmoid(y0) + EPS)
                    float sg = __fdividef(1.0f, 1.0f + __expf(-y0));
                    term = -__logf(sg + EPSV);
                } else {
                    // -log(1 - sigmoid(y0) - EPS) = -log(sigmoid(-y0) - EPS)
                    float sg = __fdividef(1.0f, 1.0f + __expf(y0));
                    term = -__logf(sg - EPSV);
                }
                total += term;
            }
        }
    }

    // warp reduce the 4 per-lane terms summed above
#pragma unroll
    for (int m = 16; m; m >>= 1) total += __shfl_xor_sync(0xffffffffu, total, m);

    __shared__ float ws[PAIRS_PER_BLOCK];
    if (lane == 0) ws[wib] = total;
    __syncthreads();
    if (threadIdx.x == 0) {
        float s = 0.0f;
#pragma unroll
        for (int w = 0; w < PAIRS_PER_BLOCK; w++) s += ws[w];
        g_block_sums[blockIdx.x] = s;
    }
}

// ---------------------------------------------------------------------------
// Kernel 3: deterministic finalize — sum block partials in double, scale.
// ---------------------------------------------------------------------------
__global__ void __launch_bounds__(1024) finalize_kernel(float* out, int nblocks, int P) {
    double s = 0.0;
    for (int i = threadIdx.x; i < nblocks; i += 1024) s += (double)g_block_sums[i];
#pragma unroll
    for (int m = 16; m; m >>= 1) s += __shfl_xor_sync(0xffffffffu, s, m);
    __shared__ double sm[32];
    int lane = threadIdx.x & 31;
    int w = threadIdx.x >> 5;
    if (lane == 0) sm[w] = s;
    __syncthreads();
    if (w == 0) {
        double v = sm[lane];
#pragma unroll
        for (int m = 16; m; m >>= 1) v += __shfl_xor_sync(0xffffffffu, v, m);
        if (lane == 0) out[0] = (float)(v / ((double)P * 64.0));
    }
}

// ---------------------------------------------------------------------------
extern "C" void kernel_launch(void* const* d_in, const int* in_sizes, int n_in,
                              void* d_out, int out_size) {
    const float* z     = (const float*)d_in[0];
    const float* alpha = (const float*)d_in[1];
    const float* beta  = (const float*)d_in[2];
    const int* ap = (const int*)d_in[3];
    const int* pp = (const int*)d_in[4];
    const int* an = (const int*)d_in[5];
    const int* nn = (const int*)d_in[6];

    int P = in_sizes[3];
    int rows = in_sizes[0] / DD;  // B * S
    if (rows > MAX_ROWS) rows = MAX_ROWS;
    int nblocks = (P + PAIRS_PER_BLOCK - 1) / PAIRS_PER_BLOCK;
    if (nblocks > MAX_BLOCKS) nblocks = MAX_BLOCKS;

    norm_kernel<<<(rows + 7) / 8, 256>>>(z, rows);
    hib_kernel<<<nblocks, 256>>>(z, alpha, beta, ap, pp, an, nn, P);
    finalize_kernel<<<1, 1024>>>((float*)d_out, nblocks, P);
}

// round 3
// speedup vs baseline: 1.0015x; 1.0015x over previous
#include <cuda_runtime.h>

// Problem constants (fixed dataset: B=16384, S=8, D=128, P=65536)
#define SB 8            // samples per item
#define DD 128          // embedding dim
#define ROW_F4 (DD / 4) // 32 float4 per row
#define PAIRS_PER_BLOCK 8
#define MAX_ROWS (16384 * SB)
#define MAX_BLOCKS 8192
#define EPSV 1e-6f

__device__ float g_norms[MAX_ROWS];
__device__ float g_block_sums[MAX_BLOCKS];

// ---------------------------------------------------------------------------
// Kernel 1: per-row squared norms. One warp per row (128 floats = 32 x float4).
// ---------------------------------------------------------------------------
__global__ void __launch_bounds__(256) norm_kernel(const float* __restrict__ z, int rows) {
    int warp = (blockIdx.x * 256 + threadIdx.x) >> 5;
    int lane = threadIdx.x & 31;
    if (warp >= rows) return;
    float4 v = reinterpret_cast<const float4*>(z)[warp * ROW_F4 + lane];
    float s = fmaf(v.x, v.x, fmaf(v.y, v.y, fmaf(v.z, v.z, v.w * v.w)));
#pragma unroll
    for (int m = 16; m; m >>= 1) s += __shfl_xor_sync(0xffffffffu, s, m);
    if (lane == 0) g_norms[warp] = s;
}

// ---------------------------------------------------------------------------
// Multi-value butterfly reduction stage: halves the live value count, pairing
// lane with lane^M. After stages 16,8,4,2,1 on 32 values, lane l holds the
// fully-reduced value with original index v == l in acc[0].
// ---------------------------------------------------------------------------
template <int M>
__device__ __forceinline__ void bfly(float* acc, int lane) {
    bool hi = (lane & M) != 0;
#pragma unroll
    for (int t = 0; t < M; t++) {
        float send = hi ? acc[t] : acc[t + M];
        float recv = __shfl_xor_sync(0xffffffffu, send, M);
        acc[t] = (hi ? acc[t + M] : acc[t]) + recv;
    }
}

// ---------------------------------------------------------------------------
// Kernel 2: main HIB criterion. One warp per pair index.
//   lane owns k-chunk [4*lane, 4*lane+4) of D=128.
//   Per matrix: load 16 rows (16 x LDG.128), 2 half-Gram (8x4) accumulations,
//   butterfly-reduce, pointwise sigmoid/log, accumulate.
// ---------------------------------------------------------------------------
__global__ void __launch_bounds__(256) hib_kernel(
    const float* __restrict__ z,
    const float* __restrict__ alpha_p,
    const float* __restrict__ beta_p,
    const int* __restrict__ ap, const int* __restrict__ pp,
    const int* __restrict__ an, const int* __restrict__ nn,
    int P)
{
    int lane = threadIdx.x & 31;
    int wib  = threadIdx.x >> 5;
    int pair = blockIdx.x * PAIRS_PER_BLOCK + wib;

    float beta = __ldg(beta_p);
    float a = log1pf(__expf(__ldg(alpha_p)));  // softplus(alpha)

    float total = 0.0f;

    if (pair < P) {
        int iA[2], iB[2];
        iA[0] = __ldg(ap + pair); iB[0] = __ldg(pp + pair);
        iA[1] = __ldg(an + pair); iB[1] = __ldg(nn + pair);

#pragma unroll
        for (int m = 0; m < 2; m++) {
            const float4* Za = reinterpret_cast<const float4*>(z) + (size_t)iA[m] * (SB * ROW_F4);
            const float4* Zb = reinterpret_cast<const float4*>(z) + (size_t)iB[m] * (SB * ROW_F4);
            float4 av[SB], bv[SB];
#pragma unroll
            for (int i = 0; i < SB; i++) av[i] = Za[i * ROW_F4 + lane];
#pragma unroll
            for (int j = 0; j < SB; j++) bv[j] = Zb[j * ROW_F4 + lane];

            // row index this lane will own after the butterfly: i = lane>>2
            float na = g_norms[iA[m] * SB + (lane >> 2)];

#pragma unroll
            for (int h = 0; h < 2; h++) {           // j in [4h, 4h+4)
                float acc[32];
#pragma unroll
                for (int i = 0; i < SB; i++) {
#pragma unroll
                    for (int jj = 0; jj < 4; jj++) {
                        float4 x = av[i];
                        float4 y = bv[h * 4 + jj];
                        acc[i * 4 + jj] =
                            fmaf(x.x, y.x, fmaf(x.y, y.y, fmaf(x.z, y.z, x.w * y.w)));
                    }
                }
                bfly<16>(acc, lane);
                bfly<8>(acc, lane);
                bfly<4>(acc, lane);
                bfly<2>(acc, lane);
                bfly<1>(acc, lane);
                // lane now holds dot(i=lane>>2, j=4h+(lane&3)) in acc[0]
                float nb = g_norms[iB[m] * SB + h * 4 + (lane & 3)];
                float d2 = na + nb - 2.0f * acc[0];
                float y0 = fmaf(-a, d2, beta);       // -a*d2 + beta
                float term;
                if (m == 0) {
                    // -log(sigmoid(y0) + EPS)
                    float sg = __fdividef(1.0f, 1.0f + __expf(-y0));
                    term = -__logf(sg + EPSV);
                } else {
                    // -log(1 - sigmoid(y0) - EPS) = -log(sigmoid(-y0) - EPS)
                    float sg = __fdividef(1.0f, 1.0f + __expf(y0));
                    term = -__logf(sg - EPSV);
                }
                total += term;
            }
        }
    }

    // warp reduce the 4 per-lane terms summed above
#pragma unroll
    for (int m = 16; m; m >>= 1) total += __shfl_xor_sync(0xffffffffu, total, m);

    __shared__ float ws[PAIRS_PER_BLOCK];
    if (lane == 0) ws[wib] = total;
    __syncthreads();
    if (threadIdx.x == 0) {
        float s = 0.0f;
#pragma unroll
        for (int w = 0; w < PAIRS_PER_BLOCK; w++) s += ws[w];
        g_block_sums[blockIdx.x] = s;
    }
}

// ---------------------------------------------------------------------------
// Kernel 3: deterministic finalize — sum block partials in double, scale.
// ---------------------------------------------------------------------------
__global__ void __launch_bounds__(1024) finalize_kernel(float* out, int nblocks, int P) {
    double s = 0.0;
    for (int i = threadIdx.x; i < nblocks; i += 1024) s += (double)g_block_sums[i];
#pragma unroll
    for (int m = 16; m; m >>= 1) s += __shfl_xor_sync(0xffffffffu, s, m);
    __shared__ double sm[32];
    int lane = threadIdx.x & 31;
    int w = threadIdx.x >> 5;
    if (lane == 0) sm[w] = s;
    __syncthreads();
    if (w == 0) {
        double v = sm[lane];
#pragma unroll
        for (int m = 16; m; m >>= 1) v += __shfl_xor_sync(0xffffffffu, v, m);
        if (lane == 0) out[0] = (float)(v / ((double)P * 64.0));
    }
}

// ---------------------------------------------------------------------------
extern "C" void kernel_launch(void* const* d_in, const int* in_sizes, int n_in,
                              void* d_out, int out_size) {
    const float* z     = (const float*)d_in[0];
    const float* alpha = (const float*)d_in[1];
    const float* beta  = (const float*)d_in[2];
    const int* ap = (const int*)d_in[3];
    const int* pp = (const int*)d_in[4];
    const int* an = (const int*)d_in[5];
    const int* nn = (const int*)d_in[6];

    int P = in_sizes[3];
    int rows = in_sizes[0] / DD;  // B * S
    if (rows > MAX_ROWS) rows = MAX_ROWS;
    int nblocks = (P + PAIRS_PER_BLOCK - 1) / PAIRS_PER_BLOCK;
    if (nblocks > MAX_BLOCKS) nblocks = MAX_BLOCKS;

    norm_kernel<<<(rows + 7) / 8, 256>>>(z, rows);
    hib_kernel<<<nblocks, 256>>>(z, alpha, beta, ap, pp, an, nn, P);
    finalize_kernel<<<1, 1024>>>((float*)d_out, nblocks, P);
}

// round 4
// speedup vs baseline: 1.0026x; 1.0011x over previous
#include <cuda_runtime.h>

// Problem constants (fixed dataset: B=16384, S=8, D=128, P=65536)
#define SB 8            // samples per item
#define DD 128          // embedding dim
#define ROW_F4 (DD / 4) // 32 float4 per row
#define PAIRS_PER_BLOCK 8
#define MAX_ROWS (16384 * SB)
#define MAX_BLOCKS 8192
#define EPSV 1e-6f

__device__ float g_norms[MAX_ROWS];
__device__ float g_block_sums[MAX_BLOCKS];

// ---------------------------------------------------------------------------
// Packed f32x2 helpers (sm_103a FFMA2 — ptxas never auto-fuses; PTX-only)
// ---------------------------------------------------------------------------
__device__ __forceinline__ unsigned long long ffma2(unsigned long long a,
                                                    unsigned long long b,
                                                    unsigned long long c) {
    unsigned long long d;
    asm("fma.rn.f32x2 %0, %1, %2, %3;" : "=l"(d) : "l"(a), "l"(b), "l"(c));
    return d;
}
__device__ __forceinline__ unsigned long long fmul2(unsigned long long a,
                                                    unsigned long long b) {
    unsigned long long d;
    asm("mul.rn.f32x2 %0, %1, %2;" : "=l"(d) : "l"(a), "l"(b));
    return d;
}
__device__ __forceinline__ float hadd2(unsigned long long v) {
    float lo, hi;
    asm("mov.b64 {%0, %1}, %2;" : "=f"(lo), "=f"(hi) : "l"(v));
    return lo + hi;
}

// ---------------------------------------------------------------------------
// Kernel 1: per-row squared norms. 8 lanes per row, 4 float4 chunks per lane
// (MLP=4 per lane, 16 LDG.128 per warp in flight) -> DRAM-bandwidth-bound.
// ---------------------------------------------------------------------------
__global__ void __launch_bounds__(256) norm_kernel(const float* __restrict__ z, int rows) {
    int warp = (blockIdx.x * 256 + threadIdx.x) >> 5;
    int lane = threadIdx.x & 31;
    int sub  = lane >> 3;   // which of 4 rows this warp handles
    int t    = lane & 7;    // chunk-lane within row
    int row  = warp * 4 + sub;
    if (row >= rows) return;
    const float4* Z = reinterpret_cast<const float4*>(z) + (size_t)row * ROW_F4;
    float4 v0 = Z[t];
    float4 v1 = Z[t + 8];
    float4 v2 = Z[t + 16];
    float4 v3 = Z[t + 24];
    float s = fmaf(v0.x, v0.x, fmaf(v0.y, v0.y, fmaf(v0.z, v0.z, v0.w * v0.w)));
    s = fmaf(v1.x, v1.x, fmaf(v1.y, v1.y, fmaf(v1.z, v1.z, fmaf(v1.w, v1.w, s))));
    s = fmaf(v2.x, v2.x, fmaf(v2.y, v2.y, fmaf(v2.z, v2.z, fmaf(v2.w, v2.w, s))));
    s = fmaf(v3.x, v3.x, fmaf(v3.y, v3.y, fmaf(v3.z, v3.z, fmaf(v3.w, v3.w, s))));
    s += __shfl_xor_sync(0xffffffffu, s, 4);
    s += __shfl_xor_sync(0xffffffffu, s, 2);
    s += __shfl_xor_sync(0xffffffffu, s, 1);
    if (t == 0) g_norms[row] = s;
}

// ---------------------------------------------------------------------------
// Multi-value butterfly reduction (identical semantics to passing R3 kernel):
// after stages 16,8,4,2,1 on 32 values, lane l holds value index l in acc[0].
// ---------------------------------------------------------------------------
template <int M>
__device__ __forceinline__ void bfly(float* acc, int lane) {
    bool hi = (lane & M) != 0;
#pragma unroll
    for (int t = 0; t < M; t++) {
        float send = hi ? acc[t] : acc[t + M];
        float recv = __shfl_xor_sync(0xffffffffu, send, M);
        acc[t] = (hi ? acc[t + M] : acc[t]) + recv;
    }
}

// ---------------------------------------------------------------------------
// One 8x8 distance matrix + pointwise loss for one (A,B) sample pair.
// Rows already resident in registers as packed f32x2 pairs (ulonglong2).
// ---------------------------------------------------------------------------
template <bool NEG>
__device__ __forceinline__ float do_matrix(
    const ulonglong2* A, const ulonglong2* B,
    float na, float nb0, float nb1,
    float a, float beta, int lane)
{
    float res = 0.0f;
#pragma unroll
    for (int h = 0; h < 2; h++) {       // j in [4h, 4h+4)
        float acc[32];
#pragma unroll
        for (int i = 0; i < SB; i++) {
#pragma unroll
            for (int jj = 0; jj < 4; jj++) {
                ulonglong2 x = A[i];
                ulonglong2 y = B[h * 4 + jj];
                // (x0*y0 + x2*y2, x1*y1 + x3*y3) then horizontal add
                acc[i * 4 + jj] = hadd2(ffma2(x.x, y.x, fmul2(x.y, y.y)));
            }
        }
        bfly<16>(acc, lane);
        bfly<8>(acc, lane);
        bfly<4>(acc, lane);
        bfly<2>(acc, lane);
        bfly<1>(acc, lane);
        // lane now holds dot(i=lane>>2, j=4h+(lane&3)) in acc[0]
        float nb = h ? nb1 : nb0;
        float d2 = (na + nb) - 2.0f * acc[0];
        float y0 = fmaf(-a, d2, beta);   // -a*d2 + beta
        if (!NEG) {
            // -log(sigmoid(y0) + EPS)
            float sg = __fdividef(1.0f, 1.0f + __expf(-y0));
            res -= __logf(sg + EPSV);
        } else {
            // -log(1 - sigmoid(y0) - EPS) = -log(sigmoid(-y0) - EPS)
            float sg = __fdividef(1.0f, 1.0f + __expf(y0));
            res -= __logf(sg - EPSV);
        }
    }
    return res;
}

// ---------------------------------------------------------------------------
// Kernel 2: main HIB criterion. One warp per pair index.
// All 32 rows (both matrices) prefetched up-front -> 32 LDG.128 in flight
// before the first FMA, hiding L2 latency for matrix 1 entirely.
// ---------------------------------------------------------------------------
__global__ void __launch_bounds__(256) hib_kernel(
    const float* __restrict__ z,
    const float* __restrict__ alpha_p,
    const float* __restrict__ beta_p,
    const int* __restrict__ ap, const int* __restrict__ pp,
    const int* __restrict__ an, const int* __restrict__ nn,
    int P)
{
    int lane = threadIdx.x & 31;
    int wib  = threadIdx.x >> 5;
    int pair = blockIdx.x * PAIRS_PER_BLOCK + wib;

    float beta = __ldg(beta_p);
    float a = log1pf(__expf(__ldg(alpha_p)));  // softplus(alpha)

    float total = 0.0f;

    if (pair < P) {
        int ia0 = __ldg(ap + pair), ib0 = __ldg(pp + pair);
        int ia1 = __ldg(an + pair), ib1 = __ldg(nn + pair);

        const ulonglong2* Z = reinterpret_cast<const ulonglong2*>(z);
        const ulonglong2* Za0 = Z + (size_t)ia0 * (SB * ROW_F4);
        const ulonglong2* Zb0 = Z + (size_t)ib0 * (SB * ROW_F4);
        const ulonglong2* Za1 = Z + (size_t)ia1 * (SB * ROW_F4);
        const ulonglong2* Zb1 = Z + (size_t)ib1 * (SB * ROW_F4);

        ulonglong2 A0[SB], B0[SB], A1[SB], B1[SB];
#pragma unroll
        for (int i = 0; i < SB; i++) A0[i] = Za0[i * ROW_F4 + lane];
#pragma unroll
        for (int i = 0; i < SB; i++) B0[i] = Zb0[i * ROW_F4 + lane];
#pragma unroll
        for (int i = 0; i < SB; i++) A1[i] = Za1[i * ROW_F4 + lane];
#pragma unroll
        for (int i = 0; i < SB; i++) B1[i] = Zb1[i * ROW_F4 + lane];

        // prefetch the norms this lane will need post-butterfly
        float na0   = g_norms[ia0 * SB + (lane >> 2)];
        float na1   = g_norms[ia1 * SB + (lane >> 2)];
        float nb0_0 = g_norms[ib0 * SB + (lane & 3)];
        float nb0_1 = g_norms[ib0 * SB + 4 + (lane & 3)];
        float nb1_0 = g_norms[ib1 * SB + (lane & 3)];
        float nb1_1 = g_norms[ib1 * SB + 4 + (lane & 3)];

        total += do_matrix<false>(A0, B0, na0, nb0_0, nb0_1, a, beta, lane);
        total += do_matrix<true >(A1, B1, na1, nb1_0, nb1_1, a, beta, lane);
    }

    // warp-reduce the 4 per-lane terms
#pragma unroll
    for (int m = 16; m; m >>= 1) total += __shfl_xor_sync(0xffffffffu, total, m);

    __shared__ float ws[PAIRS_PER_BLOCK];
    if (lane == 0) ws[wib] = total;
    __syncthreads();
    if (threadIdx.x == 0) {
        float s = 0.0f;
#pragma unroll
        for (int w = 0; w < PAIRS_PER_BLOCK; w++) s += ws[w];
        g_block_sums[blockIdx.x] = s;
    }
}

// ---------------------------------------------------------------------------
// Kernel 3: deterministic finalize — sum block partials in double, scale.
// ---------------------------------------------------------------------------
__global__ void __launch_bounds__(1024) finalize_kernel(float* out, int nblocks, int P) {
    double s = 0.0;
    for (int i = threadIdx.x; i < nblocks; i += 1024) s += (double)g_block_sums[i];
#pragma unroll
    for (int m = 16; m; m >>= 1) s += __shfl_xor_sync(0xffffffffu, s, m);
    __shared__ double sm[32];
    int lane = threadIdx.x & 31;
    int w = threadIdx.x >> 5;
    if (lane == 0) sm[w] = s;
    __syncthreads();
    if (w == 0) {
        double v = sm[lane];
#pragma unroll
        for (int m = 16; m; m >>= 1) v += __shfl_xor_sync(0xffffffffu, v, m);
        if (lane == 0) out[0] = (float)(v / ((double)P * 64.0));
    }
}

// ---------------------------------------------------------------------------
extern "C" void kernel_launch(void* const* d_in, const int* in_sizes, int n_in,
                              void* d_out, int out_size) {
    const float* z     = (const float*)d_in[0];
    const float* alpha = (const float*)d_in[1];
    const float* beta  = (const float*)d_in[2];
    const int* ap = (const int*)d_in[3];
    const int* pp = (const int*)d_in[4];
    const int* an = (const int*)d_in[5];
    const int* nn = (const int*)d_in[6];

    int P = in_sizes[3];
    int rows = in_sizes[0] / DD;  // B * S
    if (rows > MAX_ROWS) rows = MAX_ROWS;
    int nblocks = (P + PAIRS_PER_BLOCK - 1) / PAIRS_PER_BLOCK;
    if (nblocks > MAX_BLOCKS) nblocks = MAX_BLOCKS;

    int norm_warps  = (rows + 3) / 4;
    int norm_blocks = (norm_warps + 7) / 8;

    norm_kernel<<<norm_blocks, 256>>>(z, rows);
    hib_kernel<<<nblocks, 256>>>(z, alpha, beta, ap, pp, an, nn, P);
    finalize_kernel<<<1, 1024>>>((float*)d_out, nblocks, P);
}

// round 5
// speedup vs baseline: 1.4005x; 1.3969x over previous
#include <cuda_runtime.h>
#include <cuda_fp16.h>
#include <string.h>

// Fixed dataset: B=16384, S=8, D=128, P=65536
#define SB 8
#define DD 128
#define MAX_ROWS (16384 * SB)
#define PAIRS_PER_BLOCK 4
#define MAX_BLOCKS 16384
#define EPSV 1e-6f

__device__ __half g_zh[(size_t)MAX_ROWS * DD];   // 32 MB fp16 mirror of z
__device__ float g_block_sums[MAX_BLOCKS];

// ---------------------------------------------------------------------------
// Kernel 1: fp32 -> fp16 convert. Each thread converts 4 float4 (MLP=4),
// coalesced loads and stores. 96 MB total traffic, DRAM-bound.
// ---------------------------------------------------------------------------
__global__ void __launch_bounds__(256) convert_kernel(const float4* __restrict__ z4, int n4) {
    int base = blockIdx.x * 256 + threadIdx.x;
    int span = gridDim.x * 256;
    uint2* out = reinterpret_cast<uint2*>(g_zh);
#pragma unroll
    for (int k = 0; k < 4; k++) {
        int idx = base + k * span;
        if (idx < n4) {
            float4 v = z4[idx];
            __half2 h01 = __floats2half2_rn(v.x, v.y);
            __half2 h23 = __floats2half2_rn(v.z, v.w);
            uint2 o;
            memcpy(&o.x, &h01, 4);
            memcpy(&o.y, &h23, 4);
            out[idx] = o;
        }
    }
}

// ---------------------------------------------------------------------------
// 8-element half2 squared-distance partial: sum (a-b)^2 over 8 halfs,
// accumulate in half2 (all terms non-negative), horizontal add in fp32.
// ---------------------------------------------------------------------------
__device__ __forceinline__ __half2 u2h2(unsigned u) { __half2 h; memcpy(&h, &u, 4); return h; }

__device__ __forceinline__ float dsq8(uint4 a, uint4 b) {
    __half2 d, s;
    d = __hsub2(u2h2(a.x), u2h2(b.x)); s = __hmul2(d, d);
    d = __hsub2(u2h2(a.y), u2h2(b.y)); s = __hfma2(d, d, s);
    d = __hsub2(u2h2(a.z), u2h2(b.z)); s = __hfma2(d, d, s);
    d = __hsub2(u2h2(a.w), u2h2(b.w)); s = __hfma2(d, d, s);
    return __low2float(s) + __high2float(s);
}

// ---------------------------------------------------------------------------
// Multi-value butterfly stage over lane-bit B: live count HALF*2 -> HALF.
// ---------------------------------------------------------------------------
template <int B, int HALF>
__device__ __forceinline__ void bstage(float* acc, int lane) {
    bool hi = (lane & B) != 0;
#pragma unroll
    for (int t = 0; t < HALF; t++) {
        float send = hi ? acc[t] : acc[t + HALF];
        float keep = hi ? acc[t + HALF] : acc[t];
        acc[t] = keep + __shfl_xor_sync(0xffffffffu, send, B);
    }
}

// ---------------------------------------------------------------------------
// One 8x8 distance matrix + pointwise loss. Lane layout: g = lane>>4 owns
// j in [4g,4g+4); t = lane&15 owns k-chunk [8t, 8t+8). After 4 butterfly
// stages (bits 8,4,2,1) each lane holds 2 fully-reduced d2 entries.
// ---------------------------------------------------------------------------
template <bool NEG>
__device__ __forceinline__ float do_matrix(const uint4* Ah, const uint4* Bh,
                                           float a, float beta, int lane) {
    float acc[32];
#pragma unroll
    for (int i = 0; i < SB; i++)
#pragma unroll
        for (int jj = 0; jj < 4; jj++)
            acc[i * 4 + jj] = dsq8(Ah[i], Bh[jj]);

    bstage<8, 16>(acc, lane);
    bstage<4, 8>(acc, lane);
    bstage<2, 4>(acc, lane);
    bstage<1, 2>(acc, lane);

    float res = 0.0f;
#pragma unroll
    for (int c = 0; c < 2; c++) {
        float d2 = acc[c];
        float y0 = fmaf(-a, d2, beta);   // -a*d2 + beta
        if (!NEG) {
            // -log(sigmoid(y0) + EPS)
            float sg = __fdividef(1.0f, 1.0f + __expf(-y0));
            res -= __logf(sg + EPSV);
        } else {
            // -log(1 - sigmoid(y0) - EPS) = -log(sigmoid(-y0) - EPS)
            float sg = __fdividef(1.0f, 1.0f + __expf(y0));
            res -= __logf(sg - EPSV);
        }
    }
    return res;
}

// ---------------------------------------------------------------------------
// Kernel 2: main HIB criterion. One warp per pair, fp16 rows.
// Per matrix: A rows shared across both j-groups (same addresses, coalescer
// dedupes), B rows split per group. 24 LDG.128 per warp, all issued up-front.
// ---------------------------------------------------------------------------
__global__ void __launch_bounds__(128, 3) hib_kernel(
    const float* __restrict__ alpha_p,
    const float* __restrict__ beta_p,
    const int* __restrict__ ap, const int* __restrict__ pp,
    const int* __restrict__ an, const int* __restrict__ nn,
    int P)
{
    int lane = threadIdx.x & 31;
    int wib  = threadIdx.x >> 5;
    int pair = blockIdx.x * PAIRS_PER_BLOCK + wib;
    int t = lane & 15;          // k-chunk
    int g = lane >> 4;          // j-group

    float beta = __ldg(beta_p);
    float a = log1pf(__expf(__ldg(alpha_p)));  // softplus(alpha)

    float total = 0.0f;

    if (pair < P) {
        int ia0 = __ldg(ap + pair), ib0 = __ldg(pp + pair);
        int ia1 = __ldg(an + pair), ib1 = __ldg(nn + pair);

        const uint4* Z = reinterpret_cast<const uint4*>(g_zh);  // 16 uint4 per row

        uint4 A0[SB], B0[4], A1[SB], B1[4];
#pragma unroll
        for (int i = 0; i < SB; i++) A0[i] = __ldg(&Z[(size_t)(ia0 * SB + i) * 16 + t]);
#pragma unroll
        for (int r = 0; r < 4; r++) B0[r] = __ldg(&Z[(size_t)(ib0 * SB + 4 * g + r) * 16 + t]);
#pragma unroll
        for (int i = 0; i < SB; i++) A1[i] = __ldg(&Z[(size_t)(ia1 * SB + i) * 16 + t]);
#pragma unroll
        for (int r = 0; r < 4; r++) B1[r] = __ldg(&Z[(size_t)(ib1 * SB + 4 * g + r) * 16 + t]);

        total += do_matrix<false>(A0, B0, a, beta, lane);
        total += do_matrix<true >(A1, B1, a, beta, lane);
    }

    // warp-reduce per-lane partial sums
#pragma unroll
    for (int m = 16; m; m >>= 1) total += __shfl_xor_sync(0xffffffffu, total, m);

    __shared__ float ws[PAIRS_PER_BLOCK];
    if (lane == 0) ws[wib] = total;
    __syncthreads();
    if (threadIdx.x == 0) {
        float s = 0.0f;
#pragma unroll
        for (int w = 0; w < PAIRS_PER_BLOCK; w++) s += ws[w];
        g_block_sums[blockIdx.x] = s;
    }
}

// ---------------------------------------------------------------------------
// Kernel 3: deterministic finalize — sum block partials in double, scale.
// ---------------------------------------------------------------------------
__global__ void __launch_bounds__(1024) finalize_kernel(float* out, int nblocks, int P) {
    double s = 0.0;
    for (int i = threadIdx.x; i < nblocks; i += 1024) s += (double)g_block_sums[i];
#pragma unroll
    for (int m = 16; m; m >>= 1) s += __shfl_xor_sync(0xffffffffu, s, m);
    __shared__ double sm[32];
    int lane = threadIdx.x & 31;
    int w = threadIdx.x >> 5;
    if (lane == 0) sm[w] = s;
    __syncthreads();
    if (w == 0) {
        double v = sm[lane];
#pragma unroll
        for (int m = 16; m; m >>= 1) v += __shfl_xor_sync(0xffffffffu, v, m);
        if (lane == 0) out[0] = (float)(v / ((double)P * 64.0));
    }
}

// ---------------------------------------------------------------------------
extern "C" void kernel_launch(void* const* d_in, const int* in_sizes, int n_in,
                              void* d_out, int out_size) {
    const float* z     = (const float*)d_in[0];
    const float* alpha = (const float*)d_in[1];
    const float* beta  = (const float*)d_in[2];
    const int* ap = (const int*)d_in[3];
    const int* pp = (const int*)d_in[4];
    const int* an = (const int*)d_in[5];
    const int* nn = (const int*)d_in[6];

    int P = in_sizes[3];
    int rows = in_sizes[0] / DD;  // B * S
    if (rows > MAX_ROWS) rows = MAX_ROWS;

    int n4 = rows * (DD / 4);                         // float4 count
    int cblocks = (n4 + 256 * 4 - 1) / (256 * 4);     // 4 float4 per thread

    int nblocks = (P + PAIRS_PER_BLOCK - 1) / PAIRS_PER_BLOCK;
    if (nblocks > MAX_BLOCKS) nblocks = MAX_BLOCKS;

    convert_kernel<<<cblocks, 256>>>((const float4*)z, n4);
    hib_kernel<<<nblocks, 128>>>(alpha, beta, ap, pp, an, nn, P);
    finalize_kernel<<<1, 1024>>>((float*)d_out, nblocks, P);
}